// round 2
// baseline (speedup 1.0000x reference)
#include <cuda_runtime.h>
#include <cstdint>
#include <cstddef>

#define NN 65536
#define KK 1024
#define DD 128
#define BM 128
#define BK 64

typedef unsigned long long ull;

__device__ float  d_cbnorm[KK];
__device__ double d_losssum;

__device__ __forceinline__ void fma2(ull &d, ull a, ull b) {
    asm("fma.rn.f32x2 %0, %1, %2, %0;" : "+l"(d) : "l"(a), "l"(b));
}
__device__ __forceinline__ ull dup2(float x) {
    ull r; unsigned u = __float_as_uint(x);
    asm("mov.b64 %0, {%1, %1};" : "=l"(r) : "r"(u));
    return r;
}
__device__ __forceinline__ void unpack2(ull v, float &lo, float &hi) {
    unsigned a, b;
    asm("mov.b64 {%0, %1}, %2;" : "=r"(a), "=r"(b) : "l"(v));
    lo = __uint_as_float(a); hi = __uint_as_float(b);
}
__device__ __forceinline__ void upd(float v, int i, float &bv, int &bi) {
    // strict-less, tie -> smaller index (matches jnp.argmin first-occurrence)
    if (v < bv || (v == bv && i < bi)) { bv = v; bi = i; }
}

__global__ void vq_zero() { d_losssum = 0.0; }

__global__ void vq_norms(const float* __restrict__ cb) {
    int k = blockIdx.x, l = threadIdx.x;           // 32 threads, one row per block
    const float4* row = (const float4*)(cb + (size_t)k * DD);
    float4 v = row[l];
    float s = v.x*v.x + v.y*v.y + v.z*v.z + v.w*v.w;
    #pragma unroll
    for (int o = 16; o; o >>= 1) s += __shfl_down_sync(0xffffffffu, s, o);
    if (l == 0) d_cbnorm[k] = s;
}

extern __shared__ float smem_f[];

__global__ __launch_bounds__(256, 2)
void vq_main(const float* __restrict__ enc, const float* __restrict__ cb,
             float* __restrict__ out) {
    float* Ast = smem_f;             // [128][128] transposed + swizzled, 64KB
    float* Bs  = smem_f + DD * BM;   // [128][64]  transposed,            32KB
    int tid = threadIdx.x;
    int n0  = blockIdx.x * BM;

    // ---- load encoding tile, transposed with pair-granular XOR swizzle ----
    // AIDX(d,n) = d*128 + ((( n>>1 ) ^ (d & 63)) << 1) + (n & 1)
    #pragma unroll
    for (int it = 0; it < 16; ++it) {
        int idx = tid + it * 256;
        int n = idx >> 5, dv = idx & 31;
        float4 v = *(const float4*)(enc + (size_t)(n0 + n) * DD + dv * 4);
        int d0 = dv * 4;
        Ast[(d0+0)*128 + ((((n>>1) ^ ((d0+0)&63)) << 1) | (n&1))] = v.x;
        Ast[(d0+1)*128 + ((((n>>1) ^ ((d0+1)&63)) << 1) | (n&1))] = v.y;
        Ast[(d0+2)*128 + ((((n>>1) ^ ((d0+2)&63)) << 1) | (n&1))] = v.z;
        Ast[(d0+3)*128 + ((((n>>1) ^ ((d0+3)&63)) << 1) | (n&1))] = v.w;
    }

    int tx = tid & 15, ty = tid >> 4;     // tx -> 4 codes, ty -> 8 rows
    float bestv[8]; int besti[8];
    #pragma unroll
    for (int r = 0; r < 8; ++r) { bestv[r] = 3.4e38f; besti[r] = 0; }

    int codeL = tid & 63, dv0 = tid >> 6; // code-major mapping for Bs fill

    for (int k0 = 0; k0 < KK; k0 += BK) {
        __syncthreads();   // protect Bs (and first time, Ast) before overwrite
        #pragma unroll
        for (int dv = dv0; dv < 32; dv += 4) {
            float4 v = *(const float4*)(cb + (size_t)(k0 + codeL) * DD + dv * 4);
            Bs[(dv*4+0)*BK + codeL] = v.x;
            Bs[(dv*4+1)*BK + codeL] = v.y;
            Bs[(dv*4+2)*BK + codeL] = v.z;
            Bs[(dv*4+3)*BK + codeL] = v.w;
        }
        __syncthreads();

        ull acc[4][4];
        #pragma unroll
        for (int p = 0; p < 4; ++p)
            #pragma unroll
            for (int j = 0; j < 4; ++j) acc[p][j] = 0ull;

        int pb = ty * 4;  // base logical row-pair index
        #pragma unroll 8
        for (int dd = 0; dd < DD; ++dd) {
            int sw = dd & 63;
            const float* arow = Ast + dd * 128;
            ull a0 = *(const ull*)(arow + (((pb+0) ^ sw) << 1));
            ull a1 = *(const ull*)(arow + (((pb+1) ^ sw) << 1));
            ull a2 = *(const ull*)(arow + (((pb+2) ^ sw) << 1));
            ull a3 = *(const ull*)(arow + (((pb+3) ^ sw) << 1));
            float4 bq = *(const float4*)(Bs + dd * BK + tx * 4);
            ull b0 = dup2(bq.x), b1 = dup2(bq.y), b2 = dup2(bq.z), b3 = dup2(bq.w);
            fma2(acc[0][0], a0, b0); fma2(acc[0][1], a0, b1);
            fma2(acc[0][2], a0, b2); fma2(acc[0][3], a0, b3);
            fma2(acc[1][0], a1, b0); fma2(acc[1][1], a1, b1);
            fma2(acc[1][2], a1, b2); fma2(acc[1][3], a1, b3);
            fma2(acc[2][0], a2, b0); fma2(acc[2][1], a2, b1);
            fma2(acc[2][2], a2, b2); fma2(acc[2][3], a2, b3);
            fma2(acc[3][0], a3, b0); fma2(acc[3][1], a3, b1);
            fma2(acc[3][2], a3, b2); fma2(acc[3][3], a3, b3);
        }

        float4 nq = *(const float4*)(d_cbnorm + k0 + tx * 4);
        float nrm[4] = {nq.x, nq.y, nq.z, nq.w};
        #pragma unroll
        for (int p = 0; p < 4; ++p) {
            #pragma unroll
            for (int j = 0; j < 4; ++j) {
                float lo, hi; unpack2(acc[p][j], lo, hi);
                int c = k0 + tx * 4 + j;
                upd(fmaf(-2.f, lo, nrm[j]), c, bestv[2*p],     besti[2*p]);
                upd(fmaf(-2.f, hi, nrm[j]), c, bestv[2*p + 1], besti[2*p + 1]);
            }
        }
    }

    // ---- cross-thread argmin reduction (over tx) ----
    __syncthreads();
    float* sv  = Bs;                    // [128][16]
    int*   si  = (int*)(Bs + BM * 16);  // [128][16]
    int*   sidx = (int*)(Bs + BM * 32); // [128]
    #pragma unroll
    for (int r = 0; r < 8; ++r) {
        int row = ty * 8 + r;
        sv[row * 16 + tx] = bestv[r];
        si[row * 16 + tx] = besti[r];
    }
    __syncthreads();
    if (tid < BM) {
        float bv = 3.4e38f; int bi = 0;
        #pragma unroll
        for (int t = 0; t < 16; ++t) upd(sv[tid*16 + t], si[tid*16 + t], bv, bi);
        out[n0 + tid] = (float)bi;      // quantized_index (as output dtype)
        sidx[tid] = bi;
    }
    __syncthreads();

    // ---- gather + quantized_st + loss (exact JAX fp32 op sequence) ----
    float lsum = 0.f;
    #pragma unroll
    for (int it = 0; it < 16; ++it) {
        int idx = tid + it * 256;
        int n = idx >> 5, dv = idx & 31;
        int c = sidx[n];
        float4 q = *(const float4*)(cb  + (size_t)c * DD + dv * 4);
        float4 e = *(const float4*)(enc + (size_t)(n0 + n) * DD + dv * 4);
        // diff = q - e (fp32 round), st = e + diff  -- matches enc + sg(q-enc)
        float t0 = q.x - e.x, t1 = q.y - e.y, t2 = q.z - e.z, t3 = q.w - e.w;
        float4 o; o.x = e.x + t0; o.y = e.y + t1; o.z = e.z + t2; o.w = e.w + t3;
        *(float4*)(out + NN + (size_t)(n0 + n) * DD + dv * 4) = o;
        lsum += t0*t0 + t1*t1 + t2*t2 + t3*t3;
    }
    #pragma unroll
    for (int o = 16; o; o >>= 1) lsum += __shfl_down_sync(0xffffffffu, lsum, o);
    if ((tid & 31) == 0) atomicAdd(&d_losssum, (double)lsum);
}

__global__ void vq_tail(float* __restrict__ out) {
    double m = d_losssum / (double)((size_t)NN * DD);
    size_t base = (size_t)NN + (size_t)NN * DD;
    out[base + 0] = (float)(1.25 * m);  // vq_loss = 0.25*commit + embed
    out[base + 1] = (float)m;           // embedding_loss
    out[base + 2] = (float)m;           // commitment_loss
}

extern "C" void kernel_launch(void* const* d_in, const int* in_sizes, int n_in,
                              void* d_out, int out_size) {
    const float* enc = (const float*)d_in[0];
    const float* cb  = (const float*)d_in[1];
    float* out = (float*)d_out;
    (void)in_sizes; (void)n_in; (void)out_size;

    cudaFuncSetAttribute(vq_main, cudaFuncAttributeMaxDynamicSharedMemorySize,
                         96 * 1024);

    vq_zero<<<1, 1>>>();
    vq_norms<<<KK, 32>>>(cb);
    vq_main<<<NN / BM, 256, 96 * 1024>>>(enc, cb, out);
    vq_tail<<<1, 1>>>(out);
}

// round 4
// speedup vs baseline: 1.9319x; 1.9319x over previous
#include <cuda_runtime.h>
#include <cstdint>
#include <cstddef>

#define NN 65536
#define KK 1024
#define DD 128

// ---------------- device scratch (static, allocation-free) ----------------
__device__ int    d_idx[NN];
__device__ float  d_cbnorm[KK];
__device__ double d_losssum;

// ---------------- helpers ----------------
__device__ __forceinline__ float tf32r(float x) {
    uint32_t u; asm("cvt.rna.tf32.f32 %0, %1;" : "=r"(u) : "f"(x));
    return __uint_as_float(u);
}
__device__ __forceinline__ void upd(float v, int i, float& bv, int& bi) {
    // strict-less, tie -> smaller index (jnp.argmin first occurrence)
    if (v < bv || (v == bv && i < bi)) { bv = v; bi = i; }
}
__device__ __forceinline__ void mma8(float* d, const uint32_t* a, const uint32_t* b) {
    asm volatile(
        "mma.sync.aligned.m16n8k8.row.col.f32.tf32.tf32.f32 "
        "{%0,%1,%2,%3}, {%4,%5,%6,%7}, {%8,%9}, {%0,%1,%2,%3};"
        : "+f"(d[0]), "+f"(d[1]), "+f"(d[2]), "+f"(d[3])
        : "r"(a[0]), "r"(a[1]), "r"(a[2]), "r"(a[3]), "r"(b[0]), "r"(b[1]));
}

// ---------------- small kernels ----------------
__global__ void vq_zero() { d_losssum = 0.0; }

__global__ void vq_norms(const float* __restrict__ cb) {
    int k = blockIdx.x, l = threadIdx.x;
    float4 v = ((const float4*)(cb + (size_t)k * DD))[l];
    float s = v.x * v.x + v.y * v.y + v.z * v.z + v.w * v.w;
    #pragma unroll
    for (int o = 16; o; o >>= 1) s += __shfl_down_sync(0xffffffffu, s, o);
    if (l == 0) d_cbnorm[k] = s;
}

// ---------------- main mma.sync kernel ----------------
// smem layout (bytes):
//   [0, 4096)          norms (1024 f32)
//   [4096, 69632)      A hi  (128 rows x 512 B, XOR-swizzled)
//   [69632, 135168)    A lo
//   [135168, 200704)   B slabs: 2 buffers x { hi 16 KB, lo 16 KB }
//   [200704, 204800)   reduce scratch: sbv[4][128] f32, sbi[4][128] i32
#define SM_NORM 0
#define SM_AHI  4096
#define SM_ALO  69632
#define SM_B    135168
#define SM_SBV  200704
#define SM_SBI  202752
#define SM_TOT  204800

extern __shared__ char sm[];

__global__ __launch_bounds__(256, 1)
void vq_main_mma(const float* __restrict__ enc, const float* __restrict__ cb,
                 float* __restrict__ out) {
    float* norms_s = (float*)(sm + SM_NORM);
    char*  Ahi = sm + SM_AHI;
    char*  Alo = sm + SM_ALO;

    int tid  = threadIdx.x;
    int wid  = tid >> 5, lane = tid & 31;
    int g    = lane >> 2, lq = lane & 3;     // groupID, threadID_in_group
    int wm   = wid & 1,  wn = wid >> 1;      // warp M (2) x warp N (4)
    int n0   = blockIdx.x * 128;

    // norms -> smem
    ((float4*)norms_s)[tid] = ((const float4*)d_cbnorm)[tid];

    // A tile: 128 rows x 128 d, split hi/lo on load, swizzled STS
    #pragma unroll
    for (int i = 0; i < 16; ++i) {
        int idx = tid + i * 256;
        int r = idx >> 5, seg = idx & 31;
        float4 v = *(const float4*)(enc + (size_t)(n0 + r) * DD + seg * 4);
        float4 h, l;
        h.x = tf32r(v.x); l.x = tf32r(v.x - h.x);
        h.y = tf32r(v.y); l.y = tf32r(v.y - h.y);
        h.z = tf32r(v.z); l.z = tf32r(v.z - h.z);
        h.w = tf32r(v.w); l.w = tf32r(v.w - h.w);
        uint32_t off = (uint32_t)(r * 512 + ((seg * 16) ^ ((r & 7) << 4)));
        *(float4*)(Ahi + off) = h;
        *(float4*)(Alo + off) = l;
    }

    // B slab prefetch regs: slab s -> nc = s>>3 (256 codes), kc = s&7 (16 d)
    float4 pf[4];
    int pc[4], ps[4];
    #pragma unroll
    for (int j = 0; j < 4; ++j) {
        int idx = tid + j * 256;
        pc[j] = idx >> 2; ps[j] = idx & 3;
    }

    // load slab 0
    #pragma unroll
    for (int j = 0; j < 4; ++j)
        pf[j] = *(const float4*)(cb + (size_t)pc[j] * DD + ps[j] * 4);
    // STS slab 0 -> buf 0
    #pragma unroll
    for (int j = 0; j < 4; ++j) {
        uint32_t off = (uint32_t)(pc[j] * 64 + ((ps[j] * 16) ^ (((pc[j] >> 1) & 3) << 4)));
        float4 v = pf[j], h, l;
        h.x = tf32r(v.x); l.x = tf32r(v.x - h.x);
        h.y = tf32r(v.y); l.y = tf32r(v.y - h.y);
        h.z = tf32r(v.z); l.z = tf32r(v.z - h.z);
        h.w = tf32r(v.w); l.w = tf32r(v.w - h.w);
        *(float4*)(sm + SM_B + off)         = h;
        *(float4*)(sm + SM_B + 16384 + off) = l;
    }
    // load slab 1
    #pragma unroll
    for (int j = 0; j < 4; ++j)
        pf[j] = *(const float4*)(cb + ((size_t)(pc[j]) * DD + 16 + ps[j] * 4));
    __syncthreads();

    float acc[4][8][4];
    float bestv[8]; int besti[8];
    #pragma unroll
    for (int r = 0; r < 8; ++r) { bestv[r] = 3.4e38f; besti[r] = 0; }

    const uint32_t swA = (uint32_t)(g << 4);
    const uint32_t swB = (uint32_t)(((g >> 1) & 3) << 4);

    for (int s = 0; s < 32; ++s) {
        int nc = s >> 3, kc = s & 7, buf = s & 1;

        // STS slab s+1 (regs loaded last iter) into other buffer
        if (s < 31) {
            char* Bh = sm + SM_B + (buf ^ 1) * 32768;
            #pragma unroll
            for (int j = 0; j < 4; ++j) {
                uint32_t off = (uint32_t)(pc[j] * 64 + ((ps[j] * 16) ^ (((pc[j] >> 1) & 3) << 4)));
                float4 v = pf[j], h, l;
                h.x = tf32r(v.x); l.x = tf32r(v.x - h.x);
                h.y = tf32r(v.y); l.y = tf32r(v.y - h.y);
                h.z = tf32r(v.z); l.z = tf32r(v.z - h.z);
                h.w = tf32r(v.w); l.w = tf32r(v.w - h.w);
                *(float4*)(Bh + off)         = h;
                *(float4*)(Bh + 16384 + off) = l;
            }
        }
        // LDG slab s+2 -> regs
        if (s < 30) {
            int s2 = s + 2, nc2 = s2 >> 3, kc2 = s2 & 7;
            #pragma unroll
            for (int j = 0; j < 4; ++j)
                pf[j] = *(const float4*)(cb + ((size_t)(nc2 * 256 + pc[j]) * DD + kc2 * 16 + ps[j] * 4));
        }

        if (kc == 0) {
            #pragma unroll
            for (int mt = 0; mt < 4; ++mt)
                #pragma unroll
                for (int nt = 0; nt < 8; ++nt)
                    #pragma unroll
                    for (int i = 0; i < 4; ++i) acc[mt][nt][i] = 0.f;
        }

        // ---- compute slab s (3 passes x 2 k8-steps) ----
        const char* Bbuf = sm + SM_B + buf * 32768;
        #pragma unroll
        for (int pass = 0; pass < 3; ++pass) {
            const char* Ab = (pass == 2) ? Alo : Ahi;
            const char* Bb = (pass == 1) ? (Bbuf + 16384) : Bbuf;
            const char* Arow = Ab + (wm * 64 + g) * 512;
            const char* Brow = Bb + (wn * 64 + g) * 64;
            #pragma unroll
            for (int k2 = 0; k2 < 2; ++k2) {
                uint32_t kA4 = (uint32_t)((kc * 16 + k2 * 8 + lq) * 4);
                uint32_t x0 = kA4 ^ swA, x1 = (kA4 + 16) ^ swA;
                uint32_t kB4 = (uint32_t)((k2 * 8 + lq) * 4);
                uint32_t y0 = kB4 ^ swB, y1 = (kB4 + 16) ^ swB;
                uint32_t a[4][4], b[8][2];
                #pragma unroll
                for (int mt = 0; mt < 4; ++mt) {
                    const char* p = Arow + mt * 16 * 512;
                    a[mt][0] = *(const uint32_t*)(p + x0);
                    a[mt][1] = *(const uint32_t*)(p + 4096 + x0);
                    a[mt][2] = *(const uint32_t*)(p + x1);
                    a[mt][3] = *(const uint32_t*)(p + 4096 + x1);
                }
                #pragma unroll
                for (int nt = 0; nt < 8; ++nt) {
                    b[nt][0] = *(const uint32_t*)(Brow + nt * 512 + y0);
                    b[nt][1] = *(const uint32_t*)(Brow + nt * 512 + y1);
                }
                #pragma unroll
                for (int mt = 0; mt < 4; ++mt)
                    #pragma unroll
                    for (int nt = 0; nt < 8; ++nt)
                        mma8(acc[mt][nt], a[mt], b[nt]);
            }
        }

        // ---- epilogue at end of each 256-code chunk ----
        if (kc == 7) {
            #pragma unroll
            for (int mt = 0; mt < 4; ++mt)
                #pragma unroll
                for (int half = 0; half < 2; ++half) {
                    int br = mt * 2 + half;
                    float bv = bestv[br]; int bi = besti[br];
                    #pragma unroll
                    for (int nt = 0; nt < 8; ++nt) {
                        int c0 = nc * 256 + wn * 64 + nt * 8 + lq * 2;
                        float s0 = fmaf(-2.f, acc[mt][nt][half * 2 + 0], norms_s[c0]);
                        float s1 = fmaf(-2.f, acc[mt][nt][half * 2 + 1], norms_s[c0 + 1]);
                        upd(s0, c0, bv, bi);
                        upd(s1, c0 + 1, bv, bi);
                    }
                    bestv[br] = bv; besti[br] = bi;
                }
        }
        __syncthreads();
    }

    // ---- argmin reduce: quad shfl, then across wn via smem ----
    float* sbv = (float*)(sm + SM_SBV);
    int*   sbi = (int*)(sm + SM_SBI);
    #pragma unroll
    for (int mt = 0; mt < 4; ++mt)
        #pragma unroll
        for (int half = 0; half < 2; ++half) {
            int br = mt * 2 + half;
            float bv = bestv[br]; int bi = besti[br];
            #pragma unroll
            for (int o = 1; o <= 2; o <<= 1) {
                float vo = __shfl_xor_sync(0xffffffffu, bv, o);
                int   io = __shfl_xor_sync(0xffffffffu, bi, o);
                upd(vo, io, bv, bi);
            }
            if (lq == 0) {
                int r = wm * 64 + mt * 16 + half * 8 + g;
                sbv[wn * 128 + r] = bv;
                sbi[wn * 128 + r] = bi;
            }
        }
    __syncthreads();
    if (tid < 128) {
        float bv = 3.4e38f; int bi = 0x7fffffff;
        #pragma unroll
        for (int w = 0; w < 4; ++w)
            upd(sbv[w * 128 + tid], sbi[w * 128 + tid], bv, bi);
        out[n0 + tid]   = (float)bi;
        d_idx[n0 + tid] = bi;
    }
}

// ---------------- gather + quantized_st + loss (exact JAX fp op sequence) ----
__global__ __launch_bounds__(256)
void vq_finish(const float* __restrict__ enc, const float* __restrict__ cb,
               float* __restrict__ out) {
    int tid = threadIdx.x;
    int n0  = blockIdx.x * 128;
    float lsum = 0.f;
    #pragma unroll
    for (int i = 0; i < 16; ++i) {
        int idx = tid + i * 256;
        int n = idx >> 5, dv = idx & 31;
        int c = d_idx[n0 + n];
        float4 q = *(const float4*)(cb  + (size_t)c * DD + dv * 4);
        float4 e = *(const float4*)(enc + (size_t)(n0 + n) * DD + dv * 4);
        float t0 = q.x - e.x, t1 = q.y - e.y, t2 = q.z - e.z, t3 = q.w - e.w;
        float4 o; o.x = e.x + t0; o.y = e.y + t1; o.z = e.z + t2; o.w = e.w + t3;
        *(float4*)(out + NN + (size_t)(n0 + n) * DD + dv * 4) = o;
        lsum += t0 * t0 + t1 * t1 + t2 * t2 + t3 * t3;
    }
    #pragma unroll
    for (int o = 16; o; o >>= 1) lsum += __shfl_down_sync(0xffffffffu, lsum, o);
    if ((tid & 31) == 0) atomicAdd(&d_losssum, (double)lsum);
}

__global__ void vq_tail(float* __restrict__ out) {
    double m = d_losssum / (double)((size_t)NN * DD);
    size_t base = (size_t)NN + (size_t)NN * DD;
    out[base + 0] = (float)(1.25 * m);   // vq_loss
    out[base + 1] = (float)m;            // embedding_loss
    out[base + 2] = (float)m;            // commitment_loss
}

// ---------------- launch ----------------
extern "C" void kernel_launch(void* const* d_in, const int* in_sizes, int n_in,
                              void* d_out, int out_size) {
    const float* enc = (const float*)d_in[0];
    const float* cb  = (const float*)d_in[1];
    float* out = (float*)d_out;
    (void)in_sizes; (void)n_in; (void)out_size;

    cudaFuncSetAttribute(vq_main_mma, cudaFuncAttributeMaxDynamicSharedMemorySize, SM_TOT);

    vq_zero<<<1, 1>>>();
    vq_norms<<<KK, 32>>>(cb);
    vq_main_mma<<<NN / 128, 256, SM_TOT>>>(enc, cb, out);
    vq_finish<<<NN / 128, 256>>>(enc, cb, out);
    vq_tail<<<1, 1>>>(out);
}